// round 9
// baseline (speedup 1.0000x reference)
#include <cuda_runtime.h>
#include <math.h>

#define BB 4
#define DD 64
#define NV (DD*DD*DD)        // 262144 voxels per batch (2^18)
#define TOT (BB*NV)          // 1048576
#define NP 512               // points per batch
#define NCOL (TOT/64)        // 16384 z-columns
#define NTILE 256            // 4 batches * 8x8 tiles (each tile = 8x8 cols * 64 z)
// boundary work: 4 batches * 2 dirs * 7 planes * 64 rows * 64 z
#define NBW (BB*2*7*64*64)

// -------- scratch (device globals: no allocations allowed) --------
__device__ double g_part[256];
__device__ float  g_mean;
__device__ int    g_parent[TOT];                 // -1 = background
__device__ unsigned long long g_colmask[NCOL];   // foreground bits per z-column
__device__ int    g_num[BB];                     // component count per batch

// -------- 1) deterministic mean: two fixed-order tree reductions ----------
__global__ void k_reduce1(const float* __restrict__ x) {
    __shared__ double sh[256];
    const int t = threadIdx.x, bk = blockIdx.x;
    const int CH4 = (TOT / 256) / 4;       // 1024 float4 per block
    const float4* __restrict__ x4 = (const float4*)x + bk * CH4;
    double s = 0.0;
    for (int i = t; i < CH4; i += 256) {
        float4 v = x4[i];
        s += ((double)v.x + (double)v.y) + ((double)v.z + (double)v.w);
    }
    sh[t] = s; __syncthreads();
    for (int o = 128; o > 0; o >>= 1) { if (t < o) sh[t] += sh[t + o]; __syncthreads(); }
    if (t == 0) g_part[bk] = sh[0];
}

__global__ void k_reduce2() {
    __shared__ double sh[256];
    const int t = threadIdx.x;
    sh[t] = g_part[t]; __syncthreads();
    for (int o = 128; o > 0; o >>= 1) { if (t < o) sh[t] += sh[t + o]; __syncthreads(); }
    if (t == 0) g_mean = (float)(sh[0] / (double)TOT);
    if (t < BB) g_num[t] = 0;              // re-zero every replay
}

// run start of z-run containing bit z of mask m (bit z must be set)
__device__ __forceinline__ int run_start(unsigned long long m, int z) {
    const unsigned long long below =
        (z == 0) ? 0ull : (~m & ((1ull << z) - 1ull));
    return below ? (64 - __clzll(below)) : 0;
}

// -------- shared-memory UF: path-halving find + min-link union -------------
__device__ __forceinline__ int sfind(volatile int* sp, int i) {
    int p = sp[i];
    while (p != i) {
        const int gp = sp[p];
        if (gp != p) sp[i] = gp;           // halving (benign race)
        i = p; p = gp;
    }
    return i;
}

__device__ __forceinline__ void sunite(volatile int* sp, int a, int b) {
    while (true) {
        a = sfind(sp, a);
        b = sfind(sp, b);
        if (a == b) return;
        if (a > b) { const int t = a; a = b; b = t; }
        const int old = atomicMin((int*)&sp[b], a);
        if (old == b) return;
        b = old;
    }
}

// -------- 2) fused init + per-tile CCL ------------------------------------
// block = 256 threads = one tile of 8(x) * 8(y) columns * 64 z.
// thread t: column c = t>>2 (c = lx*8+ly), z chunk zb = (t&3)*16.
__global__ void k_local(const float* __restrict__ x) {
    __shared__ unsigned long long smask[64];
    __shared__ int sp_s[4096];             // per-voxel local parent
    volatile int* sp = sp_s;

    const int t  = threadIdx.x;
    const int blk = blockIdx.x;            // 0..255
    const int b  = blk >> 6;
    const int tx = (blk >> 3) & 7;
    const int ty = blk & 7;
    const int base = (b << 18) + (tx << 15) + (ty << 9);

    const int c  = t >> 2;                 // 0..63 (lx=c>>3, ly=c&7)
    const int lx = c >> 3, ly = c & 7;
    const int zb = (t & 3) << 4;           // 0,16,32,48
    const float mean = g_mean;

    // ---- build 16 mask bits from 4 float4 loads (coalesced 2KB/warp) ----
    const float* px = x + base + (lx << 12) + (ly << 6) + zb;
    unsigned int bits = 0;
    #pragma unroll
    for (int j = 0; j < 4; j++) {
        const float4 v = ((const float4*)px)[j];
        bits |= (v.x > mean ? 1u : 0u) << (4 * j);
        bits |= (v.y > mean ? 1u : 0u) << (4 * j + 1);
        bits |= (v.z > mean ? 1u : 0u) << (4 * j + 2);
        bits |= (v.w > mean ? 1u : 0u) << (4 * j + 3);
    }
    unsigned long long m = ((unsigned long long)bits) << zb;
    m |= __shfl_xor_sync(0xFFFFFFFFu, m, 1);
    m |= __shfl_xor_sync(0xFFFFFFFFu, m, 2);   // all 4 lanes: full column mask
    if ((t & 3) == 0) smask[c] = m;

    // ---- init local parents: every fg voxel -> its z-run start ----
    const int cb = c << 6;
    #pragma unroll
    for (int k = 0; k < 16; k++) {
        const int z = zb + k;
        sp_s[cb + z] = ((m >> z) & 1ull) ? (cb + run_start(m, z)) : -1;
    }
    __syncthreads();

    // ---- intra-tile column-pair unions (112 pairs, threads 0..127) ----
    if (t < 128) {
        int ca = -1, nb = -1;
        if (t < 64)       { if ((t & 7) != 0) { ca = t;       nb = ca - 1; } }  // y-pair
        else              { const int cc = t - 64;
                            if (cc >= 8)      { ca = cc;      nb = ca - 8; } }  // x-pair
        if (ca >= 0) {
            const unsigned long long mA = smask[ca];
            const unsigned long long mB = smask[nb];
            const unsigned long long ov = mA & mB;
            unsigned long long s = ov & ~(ov << 1);
            const int ba = ca << 6, bb = nb << 6;
            while (s) {
                const int z = __ffsll(s) - 1;
                s &= s - 1;
                sunite(sp, ba + run_start(mA, z), bb + run_start(mB, z));
            }
        }
    }
    __syncthreads();

    // ---- flatten + write global parents (local->global map is monotone) ----
    // local node (c<<6)|z = (lx<<9)|(ly<<6)|z ; global = base + (lx<<12)|(ly<<6)|z
    const int gbase = base + (lx << 12) + (ly << 6);
    int last_v = -2, last_g = -1;
    #pragma unroll
    for (int k = 0; k < 16; k++) {
        const int z = zb + k;
        const int v = sp_s[cb + z];
        int out;
        if (v < 0) out = -1;
        else if (v == last_v) out = last_g;        // same run -> same root
        else {
            const int r = sfind(sp, cb + z);
            out = base + ((r >> 9) << 12) + (r & 511);   // (lx<<12)|(ly<<6)|z bits
            last_v = v; last_g = out;
        }
        g_parent[gbase + z] = out;
    }
    if ((t & 3) == 0)
        g_colmask[(b << 12) + ((tx * 8 + lx) << 6) + (ty * 8 + ly)] = m;
}

// -------- global UF: path-halving find + min-link union --------------------
__device__ __forceinline__ int uf_find(int i) {
    int p = g_parent[i];
    while (p != i) {
        const int gp = g_parent[p];
        if (gp != p) g_parent[i] = gp;     // halving (benign race)
        i = p; p = gp;
    }
    return i;
}

__device__ __forceinline__ int uf_find_ro(int v) {
    int p = g_parent[v];
    while (p != v) { v = p; p = g_parent[v]; }
    return v;
}

__device__ __forceinline__ void uf_unite(int a, int b) {
    while (true) {
        a = uf_find(a);
        b = uf_find(b);
        if (a == b) return;
        if (a > b) { const int t = a; a = b; b = t; }
        const int old = atomicMin(&g_parent[b], a);
        if (old == b) return;
        b = old;
    }
}

// -------- 3) merge across tile boundaries only -----------------------------
// t: z(6b) | row(6b) | plane p(%7) | dir | batch
__global__ void k_bmerge() {
    const int t = blockIdx.x * blockDim.x + threadIdx.x;
    if (t >= NBW) return;
    const int z   = t & 63;
    const int row = (t >> 6) & 63;
    const int t3  = t >> 12;
    const int p   = t3 % 7;
    const int t4  = t3 / 7;
    const int dir = t4 & 1;
    const int b   = t4 >> 1;
    const int coord = (p + 1) << 3;        // 8,16,...,56
    int xx, yy, nbr_off;
    if (dir == 0) { xx = coord; yy = row; nbr_off = -64; }   // x-boundary
    else          { yy = coord; xx = row; nbr_off = -1;  }   // y-boundary
    const int col = (b << 12) + (xx << 6) + yy;
    const int nbr = col + nbr_off;

    const unsigned long long mA = __ldg(&g_colmask[col]);
    const unsigned long long mB = __ldg(&g_colmask[nbr]);
    const unsigned long long ov = mA & mB;
    if (!((ov >> z) & 1ull)) return;                 // no edge at this z
    if (z > 0 && ((ov >> (z - 1)) & 1ull)) return;   // not an overlap-run start

    uf_unite((col << 6) + run_start(mA, z),
             (nbr << 6) + run_start(mB, z));
}

// -------- 4) count roots: block-aggregated (one atomic per 256 voxels) -----
__global__ void k_count() {
    const int i = blockIdx.x * blockDim.x + threadIdx.x;
    const int isroot = (g_parent[i] == i) ? 1 : 0;
    const int nblk = __syncthreads_count(isroot);
    if (threadIdx.x == 0 && nblk)
        atomicAdd(&g_num[i >> 18], nblk);  // block spans one batch segment
}

// -------- 5) fused point lookup + per-batch RMS (O(P^2) in shared) --------
__global__ void k_rms(const float* __restrict__ pts, float* __restrict__ out) {
    __shared__ int sh[NP];
    __shared__ int s_h0, s_sq, s_nc;
    const int b = blockIdx.x, t = threadIdx.x;

    const float* p = pts + (b * NP + t) * 3;
    const int s0 = (int)p[0];              // pts in [0, 64-1e-3): trunc == floor
    const int s1 = (int)p[1];
    const int s2 = (int)p[2];
    const int flat = (b << 18) + (s0 << 12) + (s1 << 6) + s2;
    const int pr = g_parent[flat];
    const int h = (pr >= 0) ? (uf_find_ro(flat) + 1) : 0;

    sh[t] = h;
    if (t == 0) { s_h0 = 0; s_sq = 0; s_nc = 0; }
    __syncthreads();

    int cnt = 0, first = -1;
    #pragma unroll 8
    for (int j = 0; j < NP; j++) {
        if (sh[j] == h) { if (cnt == 0) first = j; cnt++; }
    }
    if (h == 0) {
        atomicAdd(&s_h0, 1);
    } else if (first == t) {               // representative of a hit component
        const int d = cnt - 1;
        atomicAdd(&s_sq, d * d);           // (1-cnt)^2, exact in int
        atomicAdd(&s_nc, 1);
    }
    __syncthreads();
    if (t == 0) {
        const float num = (float)g_num[b];
        const float sq = (float)s_h0 * (float)s_h0
                       + (float)s_sq
                       + (num - (float)s_nc);   // unhit components
        out[b] = sqrtf(sq / (num + 1.0f));
    }
}

// -------- launcher ----------
extern "C" void kernel_launch(void* const* d_in, const int* in_sizes, int n_in,
                              void* d_out, int out_size) {
    const float* logits = (const float*)d_in[0];
    const float* pts    = (const float*)d_in[1];
    if (n_in >= 2 && in_sizes[0] != TOT) {   // defensive input-order check
        logits = (const float*)d_in[1];
        pts    = (const float*)d_in[0];
    }
    k_reduce1<<<256, 256>>>(logits);
    k_reduce2<<<1, 256>>>();
    k_local<<<NTILE, 256>>>(logits);
    k_bmerge<<<(NBW + 255) / 256, 256>>>();
    k_count<<<TOT / 256, 256>>>();
    k_rms<<<BB, NP>>>(pts, (float*)d_out);
}

// round 10
// speedup vs baseline: 1.0517x; 1.0517x over previous
#include <cuda_runtime.h>
#include <math.h>

#define BB 4
#define DD 64
#define NV (DD*DD*DD)        // 262144 voxels per batch (2^18)
#define TOT (BB*NV)          // 1048576
#define NP 512               // points per batch
#define NCOL (TOT/64)        // 16384 z-columns
#define RSLOT 32             // run slots per column (max runs in 64 bits = 32)
#define NRUN (NCOL*RSLOT)    // 524288 run-node ids

// -------- scratch (device globals: no allocations allowed) --------
__device__ double g_part[256];
__device__ float  g_mean;
__device__ unsigned long long g_colmask[NCOL];   // foreground bits per z-column
__device__ int    g_rp[NRUN];                    // run-level UF parent; -1 = no run
__device__ int    g_num[BB];                     // component count per batch

// -------- 1) deterministic mean: two fixed-order tree reductions ----------
__global__ void k_reduce1(const float* __restrict__ x) {
    __shared__ double sh[256];
    const int t = threadIdx.x, bk = blockIdx.x;
    const int CH4 = (TOT / 256) / 4;       // 1024 float4 per block
    const float4* __restrict__ x4 = (const float4*)x + bk * CH4;
    double s = 0.0;
    for (int i = t; i < CH4; i += 256) {
        float4 v = x4[i];
        s += ((double)v.x + (double)v.y) + ((double)v.z + (double)v.w);
    }
    sh[t] = s; __syncthreads();
    for (int o = 128; o > 0; o >>= 1) { if (t < o) sh[t] += sh[t + o]; __syncthreads(); }
    if (t == 0) g_part[bk] = sh[0];
}

__global__ void k_reduce2() {
    __shared__ double sh[256];
    const int t = threadIdx.x;
    sh[t] = g_part[t]; __syncthreads();
    for (int o = 128; o > 0; o >>= 1) { if (t < o) sh[t] += sh[t + o]; __syncthreads(); }
    if (t == 0) g_mean = (float)(sh[0] / (double)TOT);
    if (t < BB) g_num[t] = 0;              // re-zero every replay
}

// bits <= z (valid for z in [0,63]; 2ull<<63 wraps to 0 -> ~0)
__device__ __forceinline__ unsigned long long mask_le(int z) {
    return (2ull << z) - 1ull;
}

// index of the run containing bit z of mask m (bit z must be set)
__device__ __forceinline__ int run_idx(unsigned long long m, int z) {
    const unsigned long long starts = m & ~(m << 1);
    return __popcll(starts & mask_le(z)) - 1;
}

// -------- 2) init: column masks + run-node UF init ------------------------
// block = 256 threads = 4 columns x 64 z
__global__ void k_init(const float* __restrict__ x) {
    __shared__ unsigned int shm[8];        // 8 half-column ballots
    const int t = threadIdx.x;
    const int z = t & 63;
    const int col = blockIdx.x * 4 + (t >> 6);
    const int i = (col << 6) + z;

    const bool fg = (x[i] > g_mean);
    const unsigned int b32 = __ballot_sync(0xFFFFFFFFu, fg);
    if ((t & 31) == 0) shm[t >> 5] = b32;
    __syncthreads();

    const int c = t >> 6;
    const unsigned long long m =
        (unsigned long long)shm[c * 2] |
        ((unsigned long long)shm[c * 2 + 1] << 32);

    if (z == 0) g_colmask[col] = m;

    // init run slots: threads z<32 each own one slot
    if (z < RSLOT) {
        const int nr = __popcll(m & ~(m << 1));
        const int id = (col << 5) + z;
        g_rp[id] = (z < nr) ? id : -1;
    }
}

// -------- run-level UF: path-halving find + min-link union -----------------
// parent ids strictly decrease toward component-min run id -> deterministic.
__device__ __forceinline__ int uf_find(int i) {
    int p = g_rp[i];
    while (p != i) {
        const int gp = g_rp[p];
        if (gp != p) g_rp[i] = gp;         // halving (benign race)
        i = p; p = gp;
    }
    return i;
}

__device__ __forceinline__ int uf_find_ro(int v) {
    int p = g_rp[v];
    while (p != v) { v = p; p = g_rp[v]; }
    return v;
}

__device__ __forceinline__ void uf_unite(int a, int b) {
    while (true) {
        a = uf_find(a);
        b = uf_find(b);
        if (a == b) return;
        if (a > b) { const int t = a; a = b; b = t; }
        const int old = atomicMin(&g_rp[b], a);
        if (old == b) return;
        b = old;
    }
}

// -------- 3) merge: one thread per (voxel, x/y-dir); dedup to run-starts ----
__global__ void k_merge() {
    const int t = blockIdx.x * blockDim.x + threadIdx.x;
    const int i = t & (TOT - 1);
    const int dir = t >> 20;               // 0: -y, 1: -x
    const int z = i & 63;
    const int col = i >> 6;
    const int y = col & 63;
    const int x = (col >> 6) & 63;
    int nbr;
    if (dir == 0) { if (y == 0) return; nbr = col - 1;  }
    else          { if (x == 0) return; nbr = col - 64; }

    const unsigned long long mA = __ldg(&g_colmask[col]);
    const unsigned long long mB = __ldg(&g_colmask[nbr]);
    const unsigned long long ov = mA & mB;
    if (!((ov >> z) & 1ull)) return;                 // no edge at this z
    if (z > 0 && ((ov >> (z - 1)) & 1ull)) return;   // not an overlap-run start

    uf_unite((col << 5) + run_idx(mA, z),
             (nbr << 5) + run_idx(mB, z));
}

// -------- 4) count roots: block-aggregated (one atomic per 256 entries) ----
__global__ void k_count() {
    const int i = blockIdx.x * blockDim.x + threadIdx.x;   // run id
    const int isroot = (g_rp[i] == i) ? 1 : 0;
    const int nblk = __syncthreads_count(isroot);
    // batch = col >> 12 = (i >> 5) >> 12 = i >> 17 ; block spans one batch
    if (threadIdx.x == 0 && nblk)
        atomicAdd(&g_num[i >> 17], nblk);
}

// -------- 5) fused point lookup + per-batch RMS (O(P^2) in shared) --------
__global__ void k_rms(const float* __restrict__ pts, float* __restrict__ out) {
    __shared__ int sh[NP];
    __shared__ int s_h0, s_sq, s_nc;
    const int b = blockIdx.x, t = threadIdx.x;

    const float* p = pts + (b * NP + t) * 3;
    const int s0 = (int)p[0];              // pts in [0, 64-1e-3): trunc == floor
    const int s1 = (int)p[1];
    const int s2 = (int)p[2];
    const int col = (b << 12) + (s0 << 6) + s1;
    const unsigned long long m = g_colmask[col];
    int h = 0;
    if ((m >> s2) & 1ull)
        h = uf_find_ro((col << 5) + run_idx(m, s2)) + 1;

    sh[t] = h;
    if (t == 0) { s_h0 = 0; s_sq = 0; s_nc = 0; }
    __syncthreads();

    int cnt = 0, first = -1;
    #pragma unroll 8
    for (int j = 0; j < NP; j++) {
        if (sh[j] == h) { if (cnt == 0) first = j; cnt++; }
    }
    if (h == 0) {
        atomicAdd(&s_h0, 1);
    } else if (first == t) {               // representative of a hit component
        const int d = cnt - 1;
        atomicAdd(&s_sq, d * d);           // (1-cnt)^2, exact in int
        atomicAdd(&s_nc, 1);
    }
    __syncthreads();
    if (t == 0) {
        const float num = (float)g_num[b];
        const float sq = (float)s_h0 * (float)s_h0
                       + (float)s_sq
                       + (num - (float)s_nc);   // unhit components
        out[b] = sqrtf(sq / (num + 1.0f));
    }
}

// -------- launcher ----------
extern "C" void kernel_launch(void* const* d_in, const int* in_sizes, int n_in,
                              void* d_out, int out_size) {
    const float* logits = (const float*)d_in[0];
    const float* pts    = (const float*)d_in[1];
    if (n_in >= 2 && in_sizes[0] != TOT) {   // defensive input-order check
        logits = (const float*)d_in[1];
        pts    = (const float*)d_in[0];
    }
    k_reduce1<<<256, 256>>>(logits);
    k_reduce2<<<1, 256>>>();
    k_init<<<TOT / 256, 256>>>(logits);
    k_merge<<<(2 * TOT) / 256, 256>>>();
    k_count<<<NRUN / 256, 256>>>();
    k_rms<<<BB, NP>>>(pts, (float*)d_out);
}